// round 1
// baseline (speedup 1.0000x reference)
#include <cuda_runtime.h>

// Problem shape is fixed by setup_inputs(): x = (2, 4, 8, 256, 256) float32.
#define BB   2
#define CC   4
#define DD   8
#define HH   256
#define WW   256
#define NBC  (BB * CC)          // 8
#define HWsz (HH * WW)          // 65536
#define DHWs (DD * HWsz)        // 524288

#define MAX_SHIFT 0.6f
#define BONUS     10.0f

// One Newton step. Returns 0 = moved (continue), 1 = converged (stop, valid),
// 2 = invalid (stop, invalid). Matches the reference iteration exactly,
// including the interleaved valid/bounds checks.
__device__ __forceinline__ int quad_step(
    float c000, float pxm, float pxp, float pym, float pyp, float psm, float psp,
    float e011, float e01m, float e0m1, float e0mm,   // (0,+1,+1) (0,+1,-1) (0,-1,+1) (0,-1,-1)
    float e101, float e10m, float em01, float em0m,   // (+1,0,+1) (+1,0,-1) (-1,0,+1) (-1,0,-1)
    float e110, float e1m0, float em10, float emm0,   // (+1,+1,0) (+1,-1,0) (-1,+1,0) (-1,-1,0)
    int& dc, int& hc, int& wc,
    float& shx, float& shy, float& shs, float& gds)
{
    float gx = 0.5f * (pxp - pxm);
    float gy = 0.5f * (pyp - pym);
    float gs = 0.5f * (psp - psm);
    float dxx = pxp - 2.0f * c000 + pxm;
    float dyy = pyp - 2.0f * c000 + pym;
    float dss = psp - 2.0f * c000 + psm;
    float dxy = 0.25f * (e011 - e01m - e0m1 + e0mm);
    float dxs = 0.25f * (e101 - e10m - em01 + em0m);
    float dys = 0.25f * (e110 - e1m0 - em10 + emm0);

    float cf00 = dyy * dss - dys * dys;
    float cf01 = dxy * dss - dys * dxs;
    float cf02 = dxy * dys - dyy * dxs;
    float det  = dxx * cf00 - dxy * cf01 + dxs * cf02;
    if (!(fabsf(det) > 0.0f)) return 2;   // solved == false -> stays invalid forever

    float r0 = -gx, r1 = -gy, r2 = -gs;
    float sx = (r0 * cf00 - dxy * (r1 * dss - dys * r2) + dxs * (r1 * dys - dyy * r2)) / det;
    float sy = (dxx * (r1 * dss - dys * r2) - r0 * cf01 + dxs * (dxy * r2 - r1 * dxs)) / det;
    float ss = (dxx * (dyy * r2 - r1 * dys) - dxy * (dxy * r2 - r1 * dxs) + r0 * cf02) / det;

    shx = sx; shy = sy; shs = ss;
    gds = gx * sx + gy * sy + gs * ss;

    // x (w) move, then bounds check
    int mvx = (sx > MAX_SHIFT) ? 1 : ((sx < -MAX_SHIFT) ? -1 : 0);
    int nw = wc + mvx;
    if (nw < 1 || nw > WW - 2) return 2;
    wc = nw;
    // y (h)
    int mvy = (sy > MAX_SHIFT) ? 1 : ((sy < -MAX_SHIFT) ? -1 : 0);
    int nh = hc + mvy;
    if (nh < 1 || nh > HH - 2) return 2;
    hc = nh;
    // s (d)
    int mvs = (ss > MAX_SHIFT) ? 1 : ((ss < -MAX_SHIFT) ? -1 : 0);
    int nd = dc + mvs;
    if (nd < 1 || nd > DD - 2) return 2;
    dc = nd;

    return ((mvx | mvy | mvs) == 0) ? 1 : 0;   // no move -> all further iters identical
}

// Block = one full W row (256 threads) at fixed (bc, d, h).
// blockIdx.x = bc*2048 + d*256 + h.
__global__ __launch_bounds__(256)
void iqi3d_kernel(const float* __restrict__ x, float* __restrict__ out)
{
    const int w  = threadIdx.x;
    const int h  = blockIdx.x & (HH - 1);
    const int d  = (blockIdx.x >> 8) & (DD - 1);
    const int bc = blockIdx.x >> 11;

    const int sp = d * HWsz + h * WW + w;
    const float* __restrict__ xb = x + (size_t)bc * DHWs;
    const float c = xb[sp];

    // defaults (coords0 channel order: [d, w, h]; y = x)
    float f_d = (float)d, f_w = (float)w, f_h = (float)h;
    float outy = c;

    __shared__ float sfull[WW];

    const bool dh_interior = (d >= 1) & (d <= DD - 2) & (h >= 1) & (h <= HH - 2);
    if (dh_interior) {   // block-uniform branch (sync is safe)
        // 3x3 (d,h) column at this w: v[dd][dh], dd/dh in {-1,0,+1} -> index 0..2
        float v[3][3];
#pragma unroll
        for (int dd = 0; dd < 3; ++dd)
#pragma unroll
            for (int dh = 0; dh < 3; ++dh)
                v[dd][dh] = xb[sp + (dd - 1) * HWsz + (dh - 1) * WW];

        float ex = v[0][0];
        ex = fmaxf(ex, v[0][1]); ex = fmaxf(ex, v[0][2]);
        ex = fmaxf(ex, v[1][0]); ex = fmaxf(ex, v[1][2]);
        ex = fmaxf(ex, v[2][0]); ex = fmaxf(ex, v[2][1]); ex = fmaxf(ex, v[2][2]);
        sfull[w] = fmaxf(ex, v[1][1]);
        __syncthreads();

        bool mask = false;
        if ((w >= 1) & (w <= WW - 2))
            mask = c > fmaxf(ex, fmaxf(sfull[w - 1], sfull[w + 1]));

        if (mask) {
            int dc = d, hc = h, wc = w;
            float shx = 0.f, shy = 0.f, shs = 0.f, gds = 0.f;

            // --- iteration 0: reuse the dw=0 plane from v, load only dw=±1 taps ---
            const float* p0 = xb + sp;   // position unchanged on iter 0 (interior)
            int st = quad_step(
                v[1][1],                      // c000
                p0[-1], p0[1],                // pxm, pxp
                v[1][0], v[1][2],             // pym, pyp
                v[0][1], v[2][1],             // psm, psp
                p0[WW + 1], p0[WW - 1], p0[-WW + 1], p0[-WW - 1],
                p0[HWsz + 1], p0[HWsz - 1], p0[-HWsz + 1], p0[-HWsz - 1],
                v[2][2], v[2][0], v[0][2], v[0][0],
                dc, hc, wc, shx, shy, shs, gds);

            // --- iterations 1..4: full 19-tap load at moved position ---
#pragma unroll 1
            for (int it = 1; (it < 5) && (st == 0); ++it) {
                int ds_ = min(max(dc, 1), DD - 2);
                int hs_ = min(max(hc, 1), HH - 2);
                int ws_ = min(max(wc, 1), WW - 2);
                const float* p = xb + ds_ * HWsz + hs_ * WW + ws_;
                st = quad_step(
                    p[0],
                    p[-1], p[1],
                    p[-WW], p[WW],
                    p[-HWsz], p[HWsz],
                    p[WW + 1], p[WW - 1], p[-WW + 1], p[-WW - 1],
                    p[HWsz + 1], p[HWsz - 1], p[-HWsz + 1], p[-HWsz - 1],
                    p[HWsz + WW], p[HWsz - WW], p[-HWsz + WW], p[-HWsz - WW],
                    dc, hc, wc, shx, shy, shs, gds);
            }

            bool valid = (st != 2)
                       && (fabsf(shx) <= 1.5f) && (fabsf(shy) <= 1.5f) && (fabsf(shs) <= 1.5f);
            if (valid) {
                f_d  = (float)dc + shs;
                f_w  = (float)wc + shx;
                f_h  = (float)hc + shy;
                outy = c + (0.5f * gds + BONUS);
            }
            // invalid-but-masked: finals fall back to (d0,w0,h0) and corr=0 -> defaults. correct.
        }
    }

    // outputs: coords_max (BC, 3, D, H, W) then y_max (BC, D, H, W)
    const int cb = bc * 3 * DHWs;
    out[cb + 0 * DHWs + sp] = f_d;
    out[cb + 1 * DHWs + sp] = f_w;
    out[cb + 2 * DHWs + sp] = f_h;
    out[(size_t)NBC * 3 * DHWs + (size_t)bc * DHWs + sp] = outy;
}

extern "C" void kernel_launch(void* const* d_in, const int* in_sizes, int n_in,
                              void* d_out, int out_size)
{
    (void)in_sizes; (void)n_in; (void)out_size;
    const float* x = (const float*)d_in[0];
    float* out = (float*)d_out;
    iqi3d_kernel<<<NBC * DD * HH, WW>>>(x, out);
}

// round 2
// speedup vs baseline: 1.0502x; 1.0502x over previous
#include <cuda_runtime.h>

// Problem shape fixed by setup_inputs(): x = (2, 4, 8, 256, 256) float32.
#define DD   8
#define HH   256
#define WW   256
#define NBC  8
#define HWsz 65536
#define DHWs 524288
#define HT   8                       // h-rows per block tile
#define NTIL (HH / HT)               // 32
#define MAIN_BLOCKS (NBC * 6 * NTIL) // 1536 (interior d = 1..6)
#define COPY_BLOCKS (NBC * 2 * NTIL) // 512  (d = 0, 7: pure defaults)

#define MAX_SHIFT 0.6f
#define BONUS     10.0f

// One Newton step. Returns 0 = moved, 1 = converged (valid), 2 = invalid.
__device__ __forceinline__ int quad_step(
    float c000, float pxm, float pxp, float pym, float pyp, float psm, float psp,
    float e011, float e01m, float e0m1, float e0mm,
    float e101, float e10m, float em01, float em0m,
    float e110, float e1m0, float em10, float emm0,
    int& dc, int& hc, int& wc,
    float& shx, float& shy, float& shs, float& gds)
{
    float gx = 0.5f * (pxp - pxm);
    float gy = 0.5f * (pyp - pym);
    float gs = 0.5f * (psp - psm);
    float dxx = pxp - 2.0f * c000 + pxm;
    float dyy = pyp - 2.0f * c000 + pym;
    float dss = psp - 2.0f * c000 + psm;
    float dxy = 0.25f * (e011 - e01m - e0m1 + e0mm);
    float dxs = 0.25f * (e101 - e10m - em01 + em0m);
    float dys = 0.25f * (e110 - e1m0 - em10 + emm0);

    float cf00 = dyy * dss - dys * dys;
    float cf01 = dxy * dss - dys * dxs;
    float cf02 = dxy * dys - dyy * dxs;
    float det  = dxx * cf00 - dxy * cf01 + dxs * cf02;
    if (!(fabsf(det) > 0.0f)) return 2;

    float r0 = -gx, r1 = -gy, r2 = -gs;
    float sx = (r0 * cf00 - dxy * (r1 * dss - dys * r2) + dxs * (r1 * dys - dyy * r2)) / det;
    float sy = (dxx * (r1 * dss - dys * r2) - r0 * cf01 + dxs * (dxy * r2 - r1 * dxs)) / det;
    float ss = (dxx * (dyy * r2 - r1 * dys) - dxy * (dxy * r2 - r1 * dxs) + r0 * cf02) / det;

    shx = sx; shy = sy; shs = ss;
    gds = gx * sx + gy * sy + gs * ss;

    int mvx = (sx > MAX_SHIFT) ? 1 : ((sx < -MAX_SHIFT) ? -1 : 0);
    int nw = wc + mvx;
    if (nw < 1 || nw > WW - 2) return 2;
    wc = nw;
    int mvy = (sy > MAX_SHIFT) ? 1 : ((sy < -MAX_SHIFT) ? -1 : 0);
    int nh = hc + mvy;
    if (nh < 1 || nh > HH - 2) return 2;
    hc = nh;
    int mvs = (ss > MAX_SHIFT) ? 1 : ((ss < -MAX_SHIFT) ? -1 : 0);
    int nd = dc + mvs;
    if (nd < 1 || nd > DD - 2) return 2;
    dc = nd;

    return ((mvx | mvy | mvs) == 0) ? 1 : 0;
}

// Full 5-iteration refinement for one masked voxel.
// Window scalars: A=h-1, B=h, C=h+1 columns; [0]=d-1, [1]=d, [2]=d+1.
// Returns (f_d, f_w, f_h, y). __noinline__: keeps the hot loop body small.
__device__ __noinline__ float4 refine(
    const float* __restrict__ xb, int sp, int d, int h, int w,
    float A0, float A1, float A2,
    float B0, float B1, float B2,
    float C0, float C1, float C2, float c)
{
    const float* p0 = xb + sp;
    int dc = d, hc = h, wc = w;
    float shx = 0.f, shy = 0.f, shs = 0.f, gds = 0.f;

    // iteration 0: reuse window for all non-x taps; 10 loads for the rest
    int st = quad_step(B1,
        p0[-1], p0[1],                 // pxm, pxp
        A1, C1,                        // pym, pyp
        B0, B2,                        // psm, psp
        p0[WW + 1], p0[WW - 1], p0[-WW + 1], p0[-WW - 1],
        p0[HWsz + 1], p0[HWsz - 1], p0[-HWsz + 1], p0[-HWsz - 1],
        C2, A2, C0, A0,
        dc, hc, wc, shx, shy, shs, gds);

#pragma unroll 1
    for (int it = 1; (it < 5) && (st == 0); ++it) {
        int ds_ = min(max(dc, 1), DD - 2);
        int hs_ = min(max(hc, 1), HH - 2);
        int ws_ = min(max(wc, 1), WW - 2);
        const float* p = xb + ds_ * HWsz + hs_ * WW + ws_;
        st = quad_step(p[0],
            p[-1], p[1], p[-WW], p[WW], p[-HWsz], p[HWsz],
            p[WW + 1], p[WW - 1], p[-WW + 1], p[-WW - 1],
            p[HWsz + 1], p[HWsz - 1], p[-HWsz + 1], p[-HWsz - 1],
            p[HWsz + WW], p[HWsz - WW], p[-HWsz + WW], p[-HWsz - WW],
            dc, hc, wc, shx, shy, shs, gds);
    }

    bool valid = (st != 2)
               && (fabsf(shx) <= 1.5f) && (fabsf(shy) <= 1.5f) && (fabsf(shs) <= 1.5f);
    if (valid)
        return make_float4((float)dc + shs, (float)wc + shx, (float)hc + shy,
                           c + (0.5f * gds + BONUS));
    return make_float4((float)d, (float)w, (float)h, c);
}

__global__ __launch_bounds__(128)
void iqi3d_kernel(const float* __restrict__ x, float* __restrict__ out)
{
    const int tid = threadIdx.x;
    const int blk = blockIdx.x;

    if (blk < MAIN_BLOCKS) {
        // ---------- main path: interior d, rolling window over h ----------
        const int t  = blk & (NTIL - 1);
        const int q  = blk >> 5;
        const int d  = (q % 6) + 1;          // 1..6
        const int bc = q / 6;
        const int h0 = t * HT;

        const float* __restrict__ xb  = x + (size_t)bc * DHWs;
        const float2* __restrict__ xb2 = (const float2*)xb;
        const int w2 = tid << 1;

        __shared__ float sfull[2][WW];

        // float2 index for column (d+dd, h): (d+dd)*32768 + h*128 + tid
        const int baseidx = d * (HWsz / 2) + tid;

        float2 A0, A1, A2, B0, B1, B2, C0, C1, C2;
        {
            int hm = h0 - 1; if (hm < 0) hm = 0;
            A0 = xb2[baseidx - (HWsz / 2) + hm * (WW / 2)];
            A1 = xb2[baseidx               + hm * (WW / 2)];
            A2 = xb2[baseidx + (HWsz / 2) + hm * (WW / 2)];
            B0 = xb2[baseidx - (HWsz / 2) + h0 * (WW / 2)];
            B1 = xb2[baseidx               + h0 * (WW / 2)];
            B2 = xb2[baseidx + (HWsz / 2) + h0 * (WW / 2)];
        }

        float* __restrict__ ob = out + (size_t)bc * 3 * DHWs + d * HWsz + h0 * WW;
        float* __restrict__ oy = out + (size_t)NBC * 3 * DHWs + (size_t)bc * DHWs
                                     + d * HWsz + h0 * WW;

        const float fw0 = (float)w2, fw1 = (float)(w2 + 1);
        const float fdd = (float)d;
        const int sp_row0 = d * HWsz + h0 * WW + w2;

#pragma unroll
        for (int r = 0; r < HT; ++r) {
            const int h = h0 + r;
            int hc1 = h + 1; if (hc1 > HH - 1) hc1 = HH - 1;
            C0 = xb2[baseidx - (HWsz / 2) + hc1 * (WW / 2)];
            C1 = xb2[baseidx               + hc1 * (WW / 2)];
            C2 = xb2[baseidx + (HWsz / 2) + hc1 * (WW / 2)];

            // per-component 26-neighbor column maxes (excluding center B1)
            float ex0 = fmaxf(A0.x, A1.x); ex0 = fmaxf(ex0, A2.x);
            ex0 = fmaxf(ex0, B0.x); ex0 = fmaxf(ex0, B2.x);
            ex0 = fmaxf(ex0, C0.x); ex0 = fmaxf(ex0, C1.x); ex0 = fmaxf(ex0, C2.x);
            float ex1 = fmaxf(A0.y, A1.y); ex1 = fmaxf(ex1, A2.y);
            ex1 = fmaxf(ex1, B0.y); ex1 = fmaxf(ex1, B2.y);
            ex1 = fmaxf(ex1, C0.y); ex1 = fmaxf(ex1, C1.y); ex1 = fmaxf(ex1, C2.y);

            const float c0 = B1.x, c1 = B1.y;
            const float full0 = fmaxf(ex0, c0), full1 = fmaxf(ex1, c1);
            const int par = r & 1;
            *(float2*)&sfull[par][w2] = make_float2(full0, full1);
            __syncthreads();
            int il = w2 - 1; if (il < 0) il = 0;
            int ir = w2 + 2; if (ir > WW - 1) ir = WW - 1;
            const float fl = sfull[par][il];
            const float fr = sfull[par][ir];

            const float fhh = (float)h;
            float fd0 = fdd, fw0o = fw0, fh0o = fhh, y0 = c0;
            float fd1 = fdd, fw1o = fw1, fh1o = fhh, y1 = c1;

            const bool hin = (h >= 1) & (h <= HH - 2);
            const bool m0 = hin & (w2 >= 1)      & (c0 > fmaxf(ex0, fmaxf(fl, full1)));
            const bool m1 = hin & (w2 <= WW - 3) & (c1 > fmaxf(ex1, fmaxf(full0, fr)));

            const int sp = sp_row0 + r * WW;

            // First masked voxel of this lane (merges the common exclusive case
            // into ONE divergent call per warp-row instead of two).
            if (m0 | m1) {
                const bool j0 = m0;
                float4 rr = refine(xb, j0 ? sp : sp + 1, d, h, j0 ? w2 : w2 + 1,
                    j0 ? A0.x : A0.y, j0 ? A1.x : A1.y, j0 ? A2.x : A2.y,
                    j0 ? B0.x : B0.y, j0 ? B1.x : B1.y, j0 ? B2.x : B2.y,
                    j0 ? C0.x : C0.y, j0 ? C1.x : C1.y, j0 ? C2.x : C2.y,
                    j0 ? c0 : c1);
                if (j0) { fd0 = rr.x; fw0o = rr.y; fh0o = rr.z; y0 = rr.w; }
                else    { fd1 = rr.x; fw1o = rr.y; fh1o = rr.z; y1 = rr.w; }
            }
            if (m0 & m1) {   // both voxels masked: rare (~0.14% of lanes)
                float4 rr = refine(xb, sp + 1, d, h, w2 + 1,
                    A0.y, A1.y, A2.y, B0.y, B1.y, B2.y, C0.y, C1.y, C2.y, c1);
                fd1 = rr.x; fw1o = rr.y; fh1o = rr.z; y1 = rr.w;
            }

            const int ro = r * WW + w2;
            *(float2*)&ob[0 * DHWs + ro] = make_float2(fd0, fd1);
            *(float2*)&ob[1 * DHWs + ro] = make_float2(fw0o, fw1o);
            *(float2*)&ob[2 * DHWs + ro] = make_float2(fh0o, fh1o);
            *(float2*)&oy[ro]            = make_float2(y0, y1);

            // roll window
            A0 = B0; A1 = B1; A2 = B2;
            B0 = C0; B1 = C1; B2 = C2;
        }
    } else {
        // ---------- copy path: d = 0 and d = 7 are pure defaults ----------
        const int blk2 = blk - MAIN_BLOCKS;
        const int t  = blk2 & (NTIL - 1);
        const int q  = blk2 >> 5;
        const int d  = (q & 1) ? (DD - 1) : 0;
        const int bc = q >> 1;
        const int h0 = t * HT;

        const float4* __restrict__ xb4 =
            (const float4*)(x + (size_t)bc * DHWs + d * HWsz + h0 * WW);
        float* __restrict__ ob = out + (size_t)bc * 3 * DHWs + d * HWsz + h0 * WW;
        float* __restrict__ oy = out + (size_t)NBC * 3 * DHWs + (size_t)bc * DHWs
                                     + d * HWsz + h0 * WW;
        const float fdd = (float)d;

#pragma unroll
        for (int i = 0; i < (HT * WW / 4) / 128; ++i) {     // 4 float4 per thread
            const int idx = i * 128 + tid;
            const int row = idx >> 6;              // 64 float4 per row
            const int wq  = (idx & 63) << 2;
            const float4 c = xb4[idx];
            const float fh = (float)(h0 + row);
            const int off = row * WW + wq;
            *(float4*)&ob[0 * DHWs + off] = make_float4(fdd, fdd, fdd, fdd);
            *(float4*)&ob[1 * DHWs + off] =
                make_float4((float)wq, (float)(wq + 1), (float)(wq + 2), (float)(wq + 3));
            *(float4*)&ob[2 * DHWs + off] = make_float4(fh, fh, fh, fh);
            *(float4*)&oy[off] = c;
        }
    }
}

extern "C" void kernel_launch(void* const* d_in, const int* in_sizes, int n_in,
                              void* d_out, int out_size)
{
    (void)in_sizes; (void)n_in; (void)out_size;
    const float* x = (const float*)d_in[0];
    float* out = (float*)d_out;
    iqi3d_kernel<<<MAIN_BLOCKS + COPY_BLOCKS, 128>>>(x, out);
}